// round 6
// baseline (speedup 1.0000x reference)
#include <cuda_runtime.h>

// ---------------------------------------------------------------------------
// BoltzmannGateSTE: out = x * (|x| >= T), T = k-th largest |x|, k = int(N/e).
// Exact radix-select on abs float bit patterns.
// Pipeline (6 launches): reset | sample+window-scan (fused, last-block) |
// main (provisional out + candidate capture via SMEM buffering) |
// round1 (12-bit hist over candidates + bin pick, fused) |
// round2 (gather selected bin + full local resolve, fused) | fixup.
// ---------------------------------------------------------------------------

#define H1        8192
#define H1_SHIFT  18
#define H2        4096
#define CAND_CAP  (4u * 1024u * 1024u)
#define GCAP      65536
#define MAIN_BLOCKS 2048
#define MAIN_THREADS 256
#define BUF       4096

__device__ unsigned g_hist1[H1];
__device__ unsigned g_hist2[H2];
__device__ unsigned g_cand_v[CAND_CAP];
__device__ unsigned g_cand_idx[CAND_CAP];
__device__ unsigned g_gath[GCAP];
__device__ unsigned g_ncand, g_cnt_hi, g_selcnt;
__device__ unsigned g_d1, g_d2, g_d3;          // done counters
__device__ unsigned g_pivot_lo, g_pivot_hi;
__device__ unsigned g_P, g_rr;
__device__ int      g_m, g_s, g_done;
__device__ unsigned g_thr;

// ---------------------------------------------------------------------------
__global__ void k_reset() {
    int t = threadIdx.x;
    for (int i = t; i < H1; i += 1024) g_hist1[i] = 0u;
    for (int i = t; i < H2; i += 1024) g_hist2[i] = 0u;
    if (t == 0) {
        g_ncand = 0u; g_cnt_hi = 0u; g_selcnt = 0u;
        g_d1 = 0u; g_d2 = 0u; g_d3 = 0u;
        g_P = 0u; g_rr = 0u; g_m = 0; g_s = 0; g_done = 0; g_thr = 0u;
    }
}

// ---------------------------------------------------------------------------
// Block-parallel descending-rank pick (256 threads). Finds the bin (in
// DESCENDING value order) containing rank rr: smallest prefix with
// cumulative >= rr. Outputs *s_selbin, *s_selnr (rank within bin), *s_tot.
__device__ __forceinline__ void pick_desc(const unsigned* bins, int nb,
                                          unsigned rr, unsigned* s_part,
                                          int* s_selbin, unsigned* s_selnr,
                                          unsigned* s_tot) {
    int t = threadIdx.x;
    int per = (nb + 255) >> 8;
    unsigned sum = 0u;
    for (int j = 0; j < per; j++) {
        int p = t * per + j;
        if (p < nb) sum += bins[nb - 1 - p];
    }
    if (t == 0) { *s_selbin = -1; *s_selnr = 0u; }
    s_part[t] = sum;
    __syncthreads();
    for (int off = 1; off < 256; off <<= 1) {
        unsigned add = (t >= off) ? s_part[t - off] : 0u;
        __syncthreads();
        s_part[t] += add;
        __syncthreads();
    }
    unsigned incl = s_part[t];
    unsigned excl = incl - sum;
    unsigned tot  = s_part[255];
    if (t == 0) *s_tot = tot;
    unsigned r = rr;
    if (r < 1u) r = 1u;
    if (tot > 0u && r > tot) r = tot;
    if (tot > 0u && excl < r && r <= incl) {
        unsigned acc = excl;
        for (int j = 0; j < per; j++) {
            int p = t * per + j;
            if (p < nb) {
                unsigned c = bins[nb - 1 - p];
                acc += c;
                if (acc >= r) { *s_selbin = nb - 1 - p; *s_selnr = r - (acc - c); break; }
            }
        }
    }
    __syncthreads();
}

// ---------------------------------------------------------------------------
// Sampling + window scan, fused. Each thread reads one float4 at a strided
// offset; blocks build SMEM hist of top-13 abs bits and merge; last block
// picks the rank window [sk-512, sk+512] (+/-1 bucket pad) and sets pivots.
__global__ void __launch_bounds__(256) k_sampleScan(const float* __restrict__ x,
                                                    int n, int nt, int stride,
                                                    long long k) {
    __shared__ unsigned h[H1];
    __shared__ unsigned s_part[256];
    __shared__ int s_selbin; __shared__ unsigned s_selnr, s_tot;
    __shared__ unsigned s_islast;
    for (int i = threadIdx.x; i < H1; i += 256) h[i] = 0u;
    __syncthreads();

    int t = blockIdx.x * 256 + threadIdx.x;
    if (t < nt) {
        long long off = (long long)t * stride;
        if (off + 3 < (long long)n) {
            float4 v = *(const float4*)(x + off);
            atomicAdd(&h[(__float_as_uint(v.x) & 0x7FFFFFFFu) >> H1_SHIFT], 1u);
            atomicAdd(&h[(__float_as_uint(v.y) & 0x7FFFFFFFu) >> H1_SHIFT], 1u);
            atomicAdd(&h[(__float_as_uint(v.z) & 0x7FFFFFFFu) >> H1_SHIFT], 1u);
            atomicAdd(&h[(__float_as_uint(v.w) & 0x7FFFFFFFu) >> H1_SHIFT], 1u);
        }
    }
    __syncthreads();
    for (int i = threadIdx.x; i < H1; i += 256) {
        unsigned c = h[i];
        if (c) atomicAdd(&g_hist1[i], c);
    }
    __threadfence();
    __syncthreads();
    if (threadIdx.x == 0) s_islast = (atomicAdd(&g_d1, 1u) == gridDim.x - 1u);
    __syncthreads();
    if (!s_islast) return;
    __threadfence();

    long long s4 = (long long)nt * 4;
    long long sk = (long long)((double)k * (double)s4 / (double)n);
    long long R1 = sk - 512; if (R1 < 1) R1 = 1;
    long long R2 = sk + 512; if (R2 < 1) R2 = 1;

    pick_desc(g_hist1, H1, (unsigned)R1, s_part, &s_selbin, &s_selnr, &s_tot);
    int bhi_raw = s_selbin; unsigned tot = s_tot;
    __syncthreads();
    pick_desc(g_hist1, H1, (unsigned)R2, s_part, &s_selbin, &s_selnr, &s_tot);
    int blo_raw = s_selbin;

    if (threadIdx.x == 0) {
        unsigned plo, phi;
        if (s4 < 4096 || tot == 0u || bhi_raw < 0 || blo_raw < 0) {
            plo = 0u; phi = 0x80000000u;   // tiny/degenerate fallback: full range
        } else {
            int bhi = bhi_raw + 1; if (bhi > H1 - 1) bhi = H1 - 1;
            int blo = blo_raw - 1; if (blo < 0) blo = 0;
            phi = ((unsigned)(bhi + 1)) << H1_SHIFT;
            plo = ((unsigned)blo) << H1_SHIFT;
        }
        unsigned width = phi - plo;
        g_pivot_lo = plo;
        g_pivot_hi = phi;
        g_m = 32 - __clz(width - 1u);
    }
}

// ---------------------------------------------------------------------------
// Full pass: provisional output + cnt_hi + candidate capture (SMEM-buffered).
// Drift bound: <=2048 adds between flush checks; flush when s_cnt > BUF-2048.
__global__ void __launch_bounds__(MAIN_THREADS) k_main(const float* __restrict__ x,
                                                       float* __restrict__ out, int n) {
    __shared__ unsigned s_v[BUF];
    __shared__ unsigned s_i[BUF];
    __shared__ unsigned s_cnt, s_base, s_hi;
    const unsigned plo = g_pivot_lo;
    const unsigned phi = g_pivot_hi;
    const int tid = threadIdx.x;
    if (tid == 0) { s_cnt = 0u; s_hi = 0u; }
    __syncthreads();

    const int n4 = n >> 2;
    const int T = gridDim.x * blockDim.x;
    const float4* x4 = (const float4*)x;
    float4* o4 = (float4*)out;
    unsigned cnt = 0u;

#pragma unroll 1
    for (int base = blockIdx.x * MAIN_THREADS; base < n4; base += 2 * T) {
        int i0 = base + tid;
        int i1 = base + T + tid;
        bool b0 = i0 < n4;
        bool b1 = i1 < n4;
        float4 v0, v1;
        if (b0) v0 = __ldcs(x4 + i0);      // streaming: batched, evict-first
        if (b1) v1 = __ldcs(x4 + i1);
        if (b0) {
            unsigned a0 = __float_as_uint(v0.x) & 0x7FFFFFFFu;
            unsigned a1 = __float_as_uint(v0.y) & 0x7FFFFFFFu;
            unsigned a2 = __float_as_uint(v0.z) & 0x7FFFFFFFu;
            unsigned a3 = __float_as_uint(v0.w) & 0x7FFFFFFFu;
            cnt += (a0 >= phi) + (a1 >= phi) + (a2 >= phi) + (a3 >= phi);
            float4 o;
            o.x = (a0 >= plo) ? v0.x : 0.0f;
            o.y = (a1 >= plo) ? v0.y : 0.0f;
            o.z = (a2 >= plo) ? v0.z : 0.0f;
            o.w = (a3 >= plo) ? v0.w : 0.0f;
            __stcs(o4 + i0, o);
            unsigned e = (unsigned)(4 * i0);
            if (a0 >= plo && a0 < phi) { unsigned p = atomicAdd(&s_cnt, 1u); s_v[p] = a0; s_i[p] = e; }
            if (a1 >= plo && a1 < phi) { unsigned p = atomicAdd(&s_cnt, 1u); s_v[p] = a1; s_i[p] = e + 1u; }
            if (a2 >= plo && a2 < phi) { unsigned p = atomicAdd(&s_cnt, 1u); s_v[p] = a2; s_i[p] = e + 2u; }
            if (a3 >= plo && a3 < phi) { unsigned p = atomicAdd(&s_cnt, 1u); s_v[p] = a3; s_i[p] = e + 3u; }
        }
        if (b1) {
            unsigned a0 = __float_as_uint(v1.x) & 0x7FFFFFFFu;
            unsigned a1 = __float_as_uint(v1.y) & 0x7FFFFFFFu;
            unsigned a2 = __float_as_uint(v1.z) & 0x7FFFFFFFu;
            unsigned a3 = __float_as_uint(v1.w) & 0x7FFFFFFFu;
            cnt += (a0 >= phi) + (a1 >= phi) + (a2 >= phi) + (a3 >= phi);
            float4 o;
            o.x = (a0 >= plo) ? v1.x : 0.0f;
            o.y = (a1 >= plo) ? v1.y : 0.0f;
            o.z = (a2 >= plo) ? v1.z : 0.0f;
            o.w = (a3 >= plo) ? v1.w : 0.0f;
            __stcs(o4 + i1, o);
            unsigned e = (unsigned)(4 * i1);
            if (a0 >= plo && a0 < phi) { unsigned p = atomicAdd(&s_cnt, 1u); s_v[p] = a0; s_i[p] = e; }
            if (a1 >= plo && a1 < phi) { unsigned p = atomicAdd(&s_cnt, 1u); s_v[p] = a1; s_i[p] = e + 1u; }
            if (a2 >= plo && a2 < phi) { unsigned p = atomicAdd(&s_cnt, 1u); s_v[p] = a2; s_i[p] = e + 2u; }
            if (a3 >= plo && a3 < phi) { unsigned p = atomicAdd(&s_cnt, 1u); s_v[p] = a3; s_i[p] = e + 3u; }
        }
        __syncthreads();
        if (s_cnt > (unsigned)(BUF - 2048)) {      // uniform after barrier
            unsigned c = s_cnt; if (c > BUF) c = BUF;
            if (tid == 0) s_base = atomicAdd(&g_ncand, c);
            __syncthreads();
            for (unsigned j = tid; j < c; j += MAIN_THREADS) {
                unsigned pos = s_base + j;
                if (pos < CAND_CAP) { g_cand_v[pos] = s_v[j]; g_cand_idx[pos] = s_i[j]; }
            }
            __syncthreads();
            if (tid == 0) s_cnt = 0u;
            __syncthreads();
        }
    }

    // scalar tail (n % 4): block 0 only, no barriers inside
    if (blockIdx.x == 0) {
        for (int e = (n4 << 2) + tid; e < n; e += MAIN_THREADS) {
            float xv = x[e];
            unsigned a = __float_as_uint(xv) & 0x7FFFFFFFu;
            cnt += (a >= phi);
            out[e] = (a >= plo) ? xv : 0.0f;
            if (a >= plo && a < phi) {
                unsigned pos = atomicAdd(&g_ncand, 1u);
                if (pos < CAND_CAP) { g_cand_v[pos] = a; g_cand_idx[pos] = (unsigned)e; }
            }
        }
    }

    __syncthreads();
    {   // final flush
        unsigned c = s_cnt; if (c > BUF) c = BUF;
        if (c) {
            if (tid == 0) s_base = atomicAdd(&g_ncand, c);
            __syncthreads();
            for (unsigned j = tid; j < c; j += MAIN_THREADS) {
                unsigned pos = s_base + j;
                if (pos < CAND_CAP) { g_cand_v[pos] = s_v[j]; g_cand_idx[pos] = s_i[j]; }
            }
        }
    }

    cnt = __reduce_add_sync(0xFFFFFFFFu, cnt);
    if ((tid & 31) == 0 && cnt) atomicAdd(&s_hi, cnt);
    __syncthreads();
    if (tid == 0 && s_hi) atomicAdd(&g_cnt_hi, s_hi);
}

// ---------------------------------------------------------------------------
// Round 1: 12-bit hist over candidates (SMEM-privatized) + fused bin pick.
// On completion: either g_done=1 with exact g_thr, or (g_P, g_s, g_rr) set
// for round 2. If done, g_s stays 0 and g_P stays 0 (k_reset defaults).
__global__ void __launch_bounds__(256) k_round1(long long k) {
    __shared__ unsigned h[H2];
    __shared__ unsigned s_part[256];
    __shared__ int s_selbin; __shared__ unsigned s_selnr, s_tot;
    __shared__ unsigned s_islast;
    const int m = g_m;
    const int nbits = (m > 12) ? 12 : m;
    const int sh = m - nbits;
    const int nb = 1 << nbits;
    const unsigned plo = g_pivot_lo;
    for (int i = threadIdx.x; i < nb; i += 256) h[i] = 0u;
    __syncthreads();

    unsigned n = g_ncand; if (n > CAND_CAP) n = CAND_CAP;
    unsigned T = gridDim.x * blockDim.x;
    for (unsigned i = blockIdx.x * blockDim.x + threadIdx.x; i < n; i += T) {
        unsigned w = g_cand_v[i] - plo;
        atomicAdd(&h[(w >> sh) & (unsigned)(nb - 1)], 1u);
    }
    __syncthreads();
    for (int i = threadIdx.x; i < nb; i += 256) {
        unsigned c = h[i];
        if (c) atomicAdd(&g_hist2[i], c);
    }
    __threadfence();
    __syncthreads();
    if (threadIdx.x == 0) s_islast = (atomicAdd(&g_d2, 1u) == gridDim.x - 1u);
    __syncthreads();
    if (!s_islast) return;
    __threadfence();

    long long rl = k - (long long)g_cnt_hi;
    if (rl < 1) rl = 1;
    unsigned rr1 = (rl > (long long)n) ? n : (unsigned)rl;
    pick_desc(g_hist2, nb, rr1, s_part, &s_selbin, &s_selnr, &s_tot);

    if (threadIdx.x == 0) {
        if (s_selbin < 0) { g_thr = plo; g_done = 1; }
        else if (sh == 0) { g_thr = plo + (unsigned)s_selbin; g_done = 1; }
        else { g_P = (unsigned)s_selbin; g_s = sh; g_rr = s_selnr; }
    }
}

// ---------------------------------------------------------------------------
// Round 2: gather candidates of selected bin; last block resolves remaining
// bits exactly with a small smem-hist loop. Uniform "skip" flag instead of a
// kernel-entry early return; when round 1 already finished, the gather loop
// is skipped and g_thr is left untouched.
__global__ void __launch_bounds__(256) k_round2() {
    __shared__ unsigned h[H2];
    __shared__ unsigned s_part[256];
    __shared__ int s_selbin; __shared__ unsigned s_selnr, s_tot;
    __shared__ unsigned s_islast;
    const int skip = g_done;            // uniform across grid
    const unsigned plo = g_pivot_lo;
    const unsigned P0 = g_P;
    const int s0 = g_s;

    if (!skip) {
        unsigned n = g_ncand; if (n > CAND_CAP) n = CAND_CAP;
        unsigned T = gridDim.x * blockDim.x;
        for (unsigned i = blockIdx.x * blockDim.x + threadIdx.x; i < n; i += T) {
            unsigned w = g_cand_v[i] - plo;
            if ((w >> s0) == P0) {
                unsigned p = atomicAdd(&g_selcnt, 1u);
                if (p < GCAP) g_gath[p] = w;
            }
        }
    }
    __threadfence();
    __syncthreads();
    if (threadIdx.x == 0) s_islast = (atomicAdd(&g_d3, 1u) == gridDim.x - 1u);
    __syncthreads();
    if (!s_islast) return;
    __threadfence();
    if (skip) return;

    unsigned cnt = g_selcnt; if (cnt > GCAP) cnt = GCAP;
    unsigned Tv = P0, rr = g_rr;
    int s = s0;
    while (s > 0) {
        int nbits = (s > 12) ? 12 : s;
        int sh = s - nbits;
        int nb = 1 << nbits;
        for (int i = threadIdx.x; i < nb; i += 256) h[i] = 0u;
        __syncthreads();
        for (unsigned i = threadIdx.x; i < cnt; i += 256) {
            unsigned w = g_gath[i];
            if ((w >> s) == Tv) atomicAdd(&h[(w >> sh) & (unsigned)(nb - 1)], 1u);
        }
        __syncthreads();
        pick_desc(h, nb, rr, s_part, &s_selbin, &s_selnr, &s_tot);
        int selbin = s_selbin;
        unsigned nr = s_selnr;
        __syncthreads();
        if (selbin < 0) break;   // degenerate; keep current prefix
        Tv = (Tv << nbits) | (unsigned)selbin;
        rr = nr;
        s = sh;
    }
    if (threadIdx.x == 0) g_thr = plo + (Tv << s);
}

// ---------------------------------------------------------------------------
// Zero the candidates below the exact threshold.
__global__ void __launch_bounds__(256) k_fix(float* __restrict__ out) {
    unsigned n = g_ncand; if (n > CAND_CAP) n = CAND_CAP;
    const unsigned thr = g_thr;
    unsigned T = gridDim.x * blockDim.x;
    for (unsigned i = blockIdx.x * blockDim.x + threadIdx.x; i < n; i += T) {
        if (g_cand_v[i] < thr) out[g_cand_idx[i]] = 0.0f;
    }
}

// ---------------------------------------------------------------------------
extern "C" void kernel_launch(void* const* d_in, const int* in_sizes, int n_in,
                              void* d_out, int out_size) {
    const float* x = (const float*)d_in[0];
    float* out = (float*)d_out;
    int n = in_sizes[0];

    // Bit-exact replication of python: k = max(1, int(n * (1.0/math.e)))
    long long k = (long long)((double)n * (1.0 / 2.718281828459045));
    if (k < 1) k = 1;

    int nt = n >> 2; if (nt > 16384) nt = 16384; if (nt < 1) nt = 1;
    int stride = (n / nt) & ~3; if (stride < 4) stride = 4;
    int sb = (nt + 255) / 256;

    k_reset<<<1, 1024>>>();
    k_sampleScan<<<sb, 256>>>(x, n, nt, stride, k);
    k_main<<<MAIN_BLOCKS, MAIN_THREADS>>>(x, out, n);
    k_round1<<<148, 256>>>(k);
    k_round2<<<148, 256>>>();
    k_fix<<<296, 256>>>(out);
}

// round 7
// speedup vs baseline: 1.0586x; 1.0586x over previous
#include <cuda_runtime.h>

// ---------------------------------------------------------------------------
// BoltzmannGateSTE: out = x * (|x| >= T), T = k-th largest |x|, k = int(N/e).
// Exact radix-select on abs float bit patterns.
// Pipeline (6 launches): reset | sample+window-scan (fused, last-block) |
// main (provisional out + candidate capture via SMEM buffering) |
// round1 (8-bit hist over candidates + fused bin pick) |
// round2 (gather selected bin + local resolve) | fixup.
// ---------------------------------------------------------------------------

#define H1        8192
#define H1_SHIFT  18
#define H2        4096
#define CAND_CAP  (4u * 1024u * 1024u)
#define GCAP      65536
#define MAIN_BLOCKS 2048
#define MAIN_THREADS 256
#define BUF       4096

__device__ unsigned g_hist1[H1];
__device__ unsigned g_hist2[H2];
__device__ unsigned g_cand_v[CAND_CAP];
__device__ unsigned g_cand_idx[CAND_CAP];
__device__ unsigned g_gath[GCAP];
__device__ unsigned g_ncand, g_cnt_hi, g_selcnt;
__device__ unsigned g_d1, g_d2, g_d3;          // done counters
__device__ unsigned g_pivot_lo, g_pivot_hi;
__device__ unsigned g_P, g_rr;
__device__ int      g_m, g_s, g_done;
__device__ unsigned g_thr;

// ---------------------------------------------------------------------------
__global__ void k_reset() {
    int t = threadIdx.x;
    for (int i = t; i < H1; i += 1024) g_hist1[i] = 0u;
    for (int i = t; i < H2; i += 1024) g_hist2[i] = 0u;
    if (t == 0) {
        g_ncand = 0u; g_cnt_hi = 0u; g_selcnt = 0u;
        g_d1 = 0u; g_d2 = 0u; g_d3 = 0u;
        g_P = 0u; g_rr = 0u; g_m = 0; g_s = 0; g_done = 0; g_thr = 0u;
    }
}

// ---------------------------------------------------------------------------
// Block-parallel descending-rank pick (256 threads). Finds the bin (in
// DESCENDING value order) containing rank rr: smallest prefix with
// cumulative >= rr. Outputs *s_selbin, *s_selnr (rank within bin), *s_tot.
__device__ __forceinline__ void pick_desc(const unsigned* bins, int nb,
                                          unsigned rr, unsigned* s_part,
                                          int* s_selbin, unsigned* s_selnr,
                                          unsigned* s_tot) {
    int t = threadIdx.x;
    int per = (nb + 255) >> 8;
    unsigned sum = 0u;
    for (int j = 0; j < per; j++) {
        int p = t * per + j;
        if (p < nb) sum += bins[nb - 1 - p];
    }
    if (t == 0) { *s_selbin = -1; *s_selnr = 0u; }
    s_part[t] = sum;
    __syncthreads();
    for (int off = 1; off < 256; off <<= 1) {
        unsigned add = (t >= off) ? s_part[t - off] : 0u;
        __syncthreads();
        s_part[t] += add;
        __syncthreads();
    }
    unsigned incl = s_part[t];
    unsigned excl = incl - sum;
    unsigned tot  = s_part[255];
    if (t == 0) *s_tot = tot;
    unsigned r = rr;
    if (r < 1u) r = 1u;
    if (tot > 0u && r > tot) r = tot;
    if (tot > 0u && excl < r && r <= incl) {
        unsigned acc = excl;
        for (int j = 0; j < per; j++) {
            int p = t * per + j;
            if (p < nb) {
                unsigned c = bins[nb - 1 - p];
                acc += c;
                if (acc >= r) { *s_selbin = nb - 1 - p; *s_selnr = r - (acc - c); break; }
            }
        }
    }
    __syncthreads();
}

// ---------------------------------------------------------------------------
// Sampling + window scan, fused. Each thread reads one float4 at a strided
// offset; blocks build SMEM hist of top-13 abs bits and merge; last block
// picks the rank window [sk-512, sk+512] (+/-1 bucket pad) and sets pivots.
__global__ void __launch_bounds__(256) k_sampleScan(const float* __restrict__ x,
                                                    int n, int nt, int stride,
                                                    long long k) {
    __shared__ unsigned h[H1];
    __shared__ unsigned s_part[256];
    __shared__ int s_selbin; __shared__ unsigned s_selnr, s_tot;
    __shared__ unsigned s_islast;
    for (int i = threadIdx.x; i < H1; i += 256) h[i] = 0u;
    __syncthreads();

    int t = blockIdx.x * 256 + threadIdx.x;
    if (t < nt) {
        long long off = (long long)t * stride;
        if (off + 3 < (long long)n) {
            float4 v = *(const float4*)(x + off);
            atomicAdd(&h[(__float_as_uint(v.x) & 0x7FFFFFFFu) >> H1_SHIFT], 1u);
            atomicAdd(&h[(__float_as_uint(v.y) & 0x7FFFFFFFu) >> H1_SHIFT], 1u);
            atomicAdd(&h[(__float_as_uint(v.z) & 0x7FFFFFFFu) >> H1_SHIFT], 1u);
            atomicAdd(&h[(__float_as_uint(v.w) & 0x7FFFFFFFu) >> H1_SHIFT], 1u);
        }
    }
    __syncthreads();
    for (int i = threadIdx.x; i < H1; i += 256) {
        unsigned c = h[i];
        if (c) atomicAdd(&g_hist1[i], c);
    }
    __threadfence();
    __syncthreads();
    if (threadIdx.x == 0) s_islast = (atomicAdd(&g_d1, 1u) == gridDim.x - 1u);
    __syncthreads();
    if (!s_islast) return;
    __threadfence();

    long long s4 = (long long)nt * 4;
    long long sk = (long long)((double)k * (double)s4 / (double)n);
    long long R1 = sk - 512; if (R1 < 1) R1 = 1;
    long long R2 = sk + 512; if (R2 < 1) R2 = 1;

    pick_desc(g_hist1, H1, (unsigned)R1, s_part, &s_selbin, &s_selnr, &s_tot);
    int bhi_raw = s_selbin; unsigned tot = s_tot;
    __syncthreads();
    pick_desc(g_hist1, H1, (unsigned)R2, s_part, &s_selbin, &s_selnr, &s_tot);
    int blo_raw = s_selbin;

    if (threadIdx.x == 0) {
        unsigned plo, phi;
        if (s4 < 4096 || tot == 0u || bhi_raw < 0 || blo_raw < 0) {
            plo = 0u; phi = 0x80000000u;   // tiny/degenerate fallback: full range
        } else {
            int bhi = bhi_raw + 1; if (bhi > H1 - 1) bhi = H1 - 1;
            int blo = blo_raw - 1; if (blo < 0) blo = 0;
            phi = ((unsigned)(bhi + 1)) << H1_SHIFT;
            plo = ((unsigned)blo) << H1_SHIFT;
        }
        unsigned width = phi - plo;
        g_pivot_lo = plo;
        g_pivot_hi = phi;
        g_m = 32 - __clz(width - 1u);
    }
}

// ---------------------------------------------------------------------------
// Full pass: provisional output + cnt_hi + candidate capture (SMEM-buffered).
// Drift bound: <=2048 adds between flush checks; flush when s_cnt > BUF-2048.
__global__ void __launch_bounds__(MAIN_THREADS) k_main(const float* __restrict__ x,
                                                       float* __restrict__ out, int n) {
    __shared__ unsigned s_v[BUF];
    __shared__ unsigned s_i[BUF];
    __shared__ unsigned s_cnt, s_base, s_hi;
    const unsigned plo = g_pivot_lo;
    const unsigned phi = g_pivot_hi;
    const int tid = threadIdx.x;
    if (tid == 0) { s_cnt = 0u; s_hi = 0u; }
    __syncthreads();

    const int n4 = n >> 2;
    const int T = gridDim.x * blockDim.x;
    const float4* x4 = (const float4*)x;
    float4* o4 = (float4*)out;
    unsigned cnt = 0u;

#pragma unroll 1
    for (int base = blockIdx.x * MAIN_THREADS; base < n4; base += 2 * T) {
        int i0 = base + tid;
        int i1 = base + T + tid;
        bool b0 = i0 < n4;
        bool b1 = i1 < n4;
        float4 v0, v1;
        if (b0) v0 = __ldcs(x4 + i0);      // streaming: batched, evict-first
        if (b1) v1 = __ldcs(x4 + i1);
        if (b0) {
            unsigned a0 = __float_as_uint(v0.x) & 0x7FFFFFFFu;
            unsigned a1 = __float_as_uint(v0.y) & 0x7FFFFFFFu;
            unsigned a2 = __float_as_uint(v0.z) & 0x7FFFFFFFu;
            unsigned a3 = __float_as_uint(v0.w) & 0x7FFFFFFFu;
            cnt += (a0 >= phi) + (a1 >= phi) + (a2 >= phi) + (a3 >= phi);
            float4 o;
            o.x = (a0 >= plo) ? v0.x : 0.0f;
            o.y = (a1 >= plo) ? v0.y : 0.0f;
            o.z = (a2 >= plo) ? v0.z : 0.0f;
            o.w = (a3 >= plo) ? v0.w : 0.0f;
            __stcs(o4 + i0, o);
            unsigned e = (unsigned)(4 * i0);
            if (a0 >= plo && a0 < phi) { unsigned p = atomicAdd(&s_cnt, 1u); s_v[p] = a0; s_i[p] = e; }
            if (a1 >= plo && a1 < phi) { unsigned p = atomicAdd(&s_cnt, 1u); s_v[p] = a1; s_i[p] = e + 1u; }
            if (a2 >= plo && a2 < phi) { unsigned p = atomicAdd(&s_cnt, 1u); s_v[p] = a2; s_i[p] = e + 2u; }
            if (a3 >= plo && a3 < phi) { unsigned p = atomicAdd(&s_cnt, 1u); s_v[p] = a3; s_i[p] = e + 3u; }
        }
        if (b1) {
            unsigned a0 = __float_as_uint(v1.x) & 0x7FFFFFFFu;
            unsigned a1 = __float_as_uint(v1.y) & 0x7FFFFFFFu;
            unsigned a2 = __float_as_uint(v1.z) & 0x7FFFFFFFu;
            unsigned a3 = __float_as_uint(v1.w) & 0x7FFFFFFFu;
            cnt += (a0 >= phi) + (a1 >= phi) + (a2 >= phi) + (a3 >= phi);
            float4 o;
            o.x = (a0 >= plo) ? v1.x : 0.0f;
            o.y = (a1 >= plo) ? v1.y : 0.0f;
            o.z = (a2 >= plo) ? v1.z : 0.0f;
            o.w = (a3 >= plo) ? v1.w : 0.0f;
            __stcs(o4 + i1, o);
            unsigned e = (unsigned)(4 * i1);
            if (a0 >= plo && a0 < phi) { unsigned p = atomicAdd(&s_cnt, 1u); s_v[p] = a0; s_i[p] = e; }
            if (a1 >= plo && a1 < phi) { unsigned p = atomicAdd(&s_cnt, 1u); s_v[p] = a1; s_i[p] = e + 1u; }
            if (a2 >= plo && a2 < phi) { unsigned p = atomicAdd(&s_cnt, 1u); s_v[p] = a2; s_i[p] = e + 2u; }
            if (a3 >= plo && a3 < phi) { unsigned p = atomicAdd(&s_cnt, 1u); s_v[p] = a3; s_i[p] = e + 3u; }
        }
        __syncthreads();
        if (s_cnt > (unsigned)(BUF - 2048)) {      // uniform after barrier
            unsigned c = s_cnt; if (c > BUF) c = BUF;
            if (tid == 0) s_base = atomicAdd(&g_ncand, c);
            __syncthreads();
            for (unsigned j = tid; j < c; j += MAIN_THREADS) {
                unsigned pos = s_base + j;
                if (pos < CAND_CAP) { g_cand_v[pos] = s_v[j]; g_cand_idx[pos] = s_i[j]; }
            }
            __syncthreads();
            if (tid == 0) s_cnt = 0u;
            __syncthreads();
        }
    }

    // scalar tail (n % 4): block 0 only, no barriers inside
    if (blockIdx.x == 0) {
        for (int e = (n4 << 2) + tid; e < n; e += MAIN_THREADS) {
            float xv = x[e];
            unsigned a = __float_as_uint(xv) & 0x7FFFFFFFu;
            cnt += (a >= phi);
            out[e] = (a >= plo) ? xv : 0.0f;
            if (a >= plo && a < phi) {
                unsigned pos = atomicAdd(&g_ncand, 1u);
                if (pos < CAND_CAP) { g_cand_v[pos] = a; g_cand_idx[pos] = (unsigned)e; }
            }
        }
    }

    __syncthreads();
    {   // final flush
        unsigned c = s_cnt; if (c > BUF) c = BUF;
        if (c) {
            if (tid == 0) s_base = atomicAdd(&g_ncand, c);
            __syncthreads();
            for (unsigned j = tid; j < c; j += MAIN_THREADS) {
                unsigned pos = s_base + j;
                if (pos < CAND_CAP) { g_cand_v[pos] = s_v[j]; g_cand_idx[pos] = s_i[j]; }
            }
        }
    }

    cnt = __reduce_add_sync(0xFFFFFFFFu, cnt);
    if ((tid & 31) == 0 && cnt) atomicAdd(&s_hi, cnt);
    __syncthreads();
    if (tid == 0 && s_hi) atomicAdd(&g_cnt_hi, s_hi);
}

// ---------------------------------------------------------------------------
// Round 1: 8-bit hist over candidates (SMEM-privatized, cheap merge: <=256
// nonzero bins per block) + fused bin pick in the last-done block.
// Vectorized uint4 reads of the candidate values.
__global__ void __launch_bounds__(256) k_round1(long long k) {
    __shared__ unsigned h[256];
    __shared__ unsigned s_part[256];
    __shared__ int s_selbin; __shared__ unsigned s_selnr, s_tot;
    __shared__ unsigned s_islast;
    const int m = g_m;
    const int nbits = (m > 8) ? 8 : m;
    const int sh = m - nbits;
    const int nb = 1 << nbits;
    const unsigned plo = g_pivot_lo;
    h[threadIdx.x] = 0u;
    __syncthreads();

    unsigned n = g_ncand; if (n > CAND_CAP) n = CAND_CAP;
    unsigned nv = n >> 2;
    unsigned T = gridDim.x * blockDim.x;
    unsigned gtid = blockIdx.x * blockDim.x + threadIdx.x;
    const uint4* cv4 = (const uint4*)g_cand_v;
    for (unsigned i = gtid; i < nv; i += T) {
        uint4 w = cv4[i];
        atomicAdd(&h[((w.x - plo) >> sh) & (unsigned)(nb - 1)], 1u);
        atomicAdd(&h[((w.y - plo) >> sh) & (unsigned)(nb - 1)], 1u);
        atomicAdd(&h[((w.z - plo) >> sh) & (unsigned)(nb - 1)], 1u);
        atomicAdd(&h[((w.w - plo) >> sh) & (unsigned)(nb - 1)], 1u);
    }
    for (unsigned i = (nv << 2) + gtid; i < n; i += T) {   // tail < 4 elements
        atomicAdd(&h[((g_cand_v[i] - plo) >> sh) & (unsigned)(nb - 1)], 1u);
    }
    __syncthreads();
    if (threadIdx.x < nb) {
        unsigned c = h[threadIdx.x];
        if (c) atomicAdd(&g_hist2[threadIdx.x], c);
    }
    __threadfence();
    __syncthreads();
    if (threadIdx.x == 0) s_islast = (atomicAdd(&g_d2, 1u) == gridDim.x - 1u);
    __syncthreads();
    if (!s_islast) return;
    __threadfence();

    long long rl = k - (long long)g_cnt_hi;
    if (rl < 1) rl = 1;
    unsigned rr1 = (rl > (long long)n) ? n : (unsigned)rl;
    pick_desc(g_hist2, nb, rr1, s_part, &s_selbin, &s_selnr, &s_tot);

    if (threadIdx.x == 0) {
        if (s_selbin < 0) { g_thr = plo; g_done = 1; }
        else if (sh == 0) { g_thr = plo + (unsigned)s_selbin; g_done = 1; }
        else { g_P = (unsigned)s_selbin; g_s = sh; g_rr = s_selnr; }
    }
}

// ---------------------------------------------------------------------------
// Round 2: gather candidates of selected bin (vectorized reads); last-done
// block resolves remaining bits exactly with a small smem-hist loop.
__global__ void __launch_bounds__(256) k_round2() {
    __shared__ unsigned h[H2];
    __shared__ unsigned s_part[256];
    __shared__ int s_selbin; __shared__ unsigned s_selnr, s_tot;
    __shared__ unsigned s_islast;
    const int skip = g_done;            // uniform across grid
    const unsigned plo = g_pivot_lo;
    const unsigned P0 = g_P;
    const int s0 = g_s;

    if (!skip) {
        unsigned n = g_ncand; if (n > CAND_CAP) n = CAND_CAP;
        unsigned nv = n >> 2;
        unsigned T = gridDim.x * blockDim.x;
        unsigned gtid = blockIdx.x * blockDim.x + threadIdx.x;
        const uint4* cv4 = (const uint4*)g_cand_v;
        for (unsigned i = gtid; i < nv; i += T) {
            uint4 wv = cv4[i];
            unsigned w;
            w = wv.x - plo; if ((w >> s0) == P0) { unsigned p = atomicAdd(&g_selcnt, 1u); if (p < GCAP) g_gath[p] = w; }
            w = wv.y - plo; if ((w >> s0) == P0) { unsigned p = atomicAdd(&g_selcnt, 1u); if (p < GCAP) g_gath[p] = w; }
            w = wv.z - plo; if ((w >> s0) == P0) { unsigned p = atomicAdd(&g_selcnt, 1u); if (p < GCAP) g_gath[p] = w; }
            w = wv.w - plo; if ((w >> s0) == P0) { unsigned p = atomicAdd(&g_selcnt, 1u); if (p < GCAP) g_gath[p] = w; }
        }
        for (unsigned i = (nv << 2) + gtid; i < n; i += T) {
            unsigned w = g_cand_v[i] - plo;
            if ((w >> s0) == P0) { unsigned p = atomicAdd(&g_selcnt, 1u); if (p < GCAP) g_gath[p] = w; }
        }
    }
    __threadfence();
    __syncthreads();
    if (threadIdx.x == 0) s_islast = (atomicAdd(&g_d3, 1u) == gridDim.x - 1u);
    __syncthreads();
    if (!s_islast) return;
    __threadfence();
    if (skip) return;

    unsigned cnt = g_selcnt; if (cnt > GCAP) cnt = GCAP;
    unsigned Tv = P0, rr = g_rr;
    int s = s0;
    while (s > 0) {
        int nbits = (s > 12) ? 12 : s;
        int sh = s - nbits;
        int nb = 1 << nbits;
        for (int i = threadIdx.x; i < nb; i += 256) h[i] = 0u;
        __syncthreads();
        for (unsigned i = threadIdx.x; i < cnt; i += 256) {
            unsigned w = g_gath[i];
            if ((w >> s) == Tv) atomicAdd(&h[(w >> sh) & (unsigned)(nb - 1)], 1u);
        }
        __syncthreads();
        pick_desc(h, nb, rr, s_part, &s_selbin, &s_selnr, &s_tot);
        int selbin = s_selbin;
        unsigned nr = s_selnr;
        __syncthreads();
        if (selbin < 0) break;   // degenerate; keep current prefix
        Tv = (Tv << nbits) | (unsigned)selbin;
        rr = nr;
        s = sh;
    }
    if (threadIdx.x == 0) g_thr = plo + (Tv << s);
}

// ---------------------------------------------------------------------------
// Zero the candidates below the exact threshold (vectorized reads).
__global__ void __launch_bounds__(256) k_fix(float* __restrict__ out) {
    unsigned n = g_ncand; if (n > CAND_CAP) n = CAND_CAP;
    const unsigned thr = g_thr;
    unsigned nv = n >> 2;
    unsigned T = gridDim.x * blockDim.x;
    unsigned gtid = blockIdx.x * blockDim.x + threadIdx.x;
    const uint4* cv4 = (const uint4*)g_cand_v;
    const uint4* ci4 = (const uint4*)g_cand_idx;
    for (unsigned i = gtid; i < nv; i += T) {
        uint4 v = cv4[i];
        uint4 ix = ci4[i];
        if (v.x < thr) out[ix.x] = 0.0f;
        if (v.y < thr) out[ix.y] = 0.0f;
        if (v.z < thr) out[ix.z] = 0.0f;
        if (v.w < thr) out[ix.w] = 0.0f;
    }
    for (unsigned i = (nv << 2) + gtid; i < n; i += T) {
        if (g_cand_v[i] < thr) out[g_cand_idx[i]] = 0.0f;
    }
}

// ---------------------------------------------------------------------------
extern "C" void kernel_launch(void* const* d_in, const int* in_sizes, int n_in,
                              void* d_out, int out_size) {
    const float* x = (const float*)d_in[0];
    float* out = (float*)d_out;
    int n = in_sizes[0];

    // Bit-exact replication of python: k = max(1, int(n * (1.0/math.e)))
    long long k = (long long)((double)n * (1.0 / 2.718281828459045));
    if (k < 1) k = 1;

    int nt = n >> 2; if (nt > 16384) nt = 16384; if (nt < 1) nt = 1;
    int stride = (n / nt) & ~3; if (stride < 4) stride = 4;
    int sb = (nt + 255) / 256;

    k_reset<<<1, 1024>>>();
    k_sampleScan<<<sb, 256>>>(x, n, nt, stride, k);
    k_main<<<MAIN_BLOCKS, MAIN_THREADS>>>(x, out, n);
    k_round1<<<592, 256>>>(k);
    k_round2<<<592, 256>>>();
    k_fix<<<1184, 256>>>(out);
}